// round 7
// baseline (speedup 1.0000x reference)
#include <cuda_runtime.h>
#include <cuda_bf16.h>
#include <cstdint>

// Problem constants
#define B     32
#define IN_CH 512
#define VD    16
#define HW    4096          // 64*64
#define NCLS  5

typedef unsigned long long ULL;

// ---------------- device scratch (no allocs allowed) ----------------
__device__ float g_v[(size_t)B * HW * VD];   // 8 MB: root conv output, (b, pix, 16)
__device__ float g_part[128 * VD];           // per-block partial sums of v (for mean)
__device__ float g_Asel[B * VD * VD];        // selected leaf composition matrix
__device__ float g_dvec[B * VD];             // selected leaf offset (A@root_b + c)
__device__ float g_m2part[256];              // per-block partial sums of m2

__device__ __forceinline__ ULL ffma2(ULL a, ULL b, ULL c) {
    ULL d;
    asm("fma.rn.f32x2 %0, %1, %2, %3;" : "=l"(d) : "l"(a), "l"(b), "l"(c));
    return d;
}

// ======================================================================
// Pass 1: v[b,pix,:] = root_w @ features[b,:,pix]  (+ per-block partial sums)
// 256 threads/block, 4 consecutive pixels per thread (2 x f32x2 pairs),
// 4 blocks per batch -> grid 128 (single wave on 148 SMs).
// ======================================================================
__global__ void __launch_bounds__(256) k_root(const float* __restrict__ feat,
                                              const float* __restrict__ root_w) {
    extern __shared__ ULL s_w[];   // [512][16] duplicated (w,w) pairs = 64 KB
    const int b     = blockIdx.x >> 2;
    const int chunk = blockIdx.x & 3;
    const int tid   = threadIdx.x;

    for (int idx = tid; idx < IN_CH * VD; idx += 256) {
        int c = idx >> 4, o = idx & 15;
        float w = root_w[o * IN_CH + c];
        float2 t = make_float2(w, w);
        s_w[idx] = *reinterpret_cast<ULL*>(&t);
    }
    __syncthreads();

    const int pix0 = chunk * 1024 + tid * 4;
    const float* fp = feat + (size_t)b * (IN_CH * HW) + pix0;

    ULL acc0[VD], acc1[VD];
    {
        float2 z = make_float2(0.f, 0.f);
        ULL zu = *reinterpret_cast<ULL*>(&z);
#pragma unroll
        for (int o = 0; o < VD; o++) { acc0[o] = zu; acc1[o] = zu; }
    }

#pragma unroll 2
    for (int c = 0; c < IN_CH; c++) {
        // pixels [pix0, pix0+3]: 16B aligned, coalesced 512B/warp
        ulonglong2 x = *reinterpret_cast<const ulonglong2*>(fp + (size_t)c * HW);
        const ulonglong2* wv = reinterpret_cast<const ulonglong2*>(s_w + c * VD);
#pragma unroll
        for (int q = 0; q < 8; q++) {
            ulonglong2 wp = wv[q];
            acc0[2 * q + 0] = ffma2(wp.x, x.x, acc0[2 * q + 0]);
            acc0[2 * q + 1] = ffma2(wp.y, x.x, acc0[2 * q + 1]);
            acc1[2 * q + 0] = ffma2(wp.x, x.y, acc1[2 * q + 0]);
            acc1[2 * q + 1] = ffma2(wp.y, x.y, acc1[2 * q + 1]);
        }
    }

    // unpack: acc0[o] = (pix0, pix0+1), acc1[o] = (pix0+2, pix0+3)
    float p0[VD], p1[VD], p2[VD], p3[VD];
#pragma unroll
    for (int o = 0; o < VD; o++) {
        float2 t0 = *reinterpret_cast<float2*>(&acc0[o]);
        float2 t1 = *reinterpret_cast<float2*>(&acc1[o]);
        p0[o] = t0.x; p1[o] = t0.y; p2[o] = t1.x; p3[o] = t1.y;
    }

    // store v (pixel-major, 16 contiguous floats per pixel) -> 256B/thread
    float4* vp = reinterpret_cast<float4*>(g_v + ((size_t)b * HW + pix0) * VD);
#pragma unroll
    for (int q = 0; q < 4; q++) {
        vp[0 * 4 + q] = make_float4(p0[4*q], p0[4*q+1], p0[4*q+2], p0[4*q+3]);
        vp[1 * 4 + q] = make_float4(p1[4*q], p1[4*q+1], p1[4*q+2], p1[4*q+3]);
        vp[2 * 4 + q] = make_float4(p2[4*q], p2[4*q+1], p2[4*q+2], p2[4*q+3]);
        vp[3 * 4 + q] = make_float4(p3[4*q], p3[4*q+1], p3[4*q+2], p3[4*q+3]);
    }

    // block reduction of per-pixel sums (deterministic; no atomics)
    __shared__ float red[8][VD];
    const int lane = tid & 31, wid = tid >> 5;
#pragma unroll
    for (int o = 0; o < VD; o++) {
        float s = (p0[o] + p1[o]) + (p2[o] + p3[o]);
#pragma unroll
        for (int off = 16; off; off >>= 1) s += __shfl_xor_sync(0xffffffffu, s, off);
        if (lane == 0) red[wid][o] = s;
    }
    __syncthreads();
    if (tid < VD) {
        float t = 0.f;
#pragma unroll
        for (int w = 0; w < 8; w++) t += red[w][tid];
        g_part[blockIdx.x * VD + tid] = t;
    }
}

// ======================================================================
// Pass 2: per-batch tree recursion on pooled means. One block per batch.
// Tracks (A, c) composition per node + pooled mean mu per node.
// Writes class_logits, selected_class; stores A_sel and dvec for pass 3.
// ======================================================================
__global__ void __launch_bounds__(256) k_tree(const float* __restrict__ root_b,
                                              const float* __restrict__ level_w,
                                              const float* __restrict__ level_b,
                                              float* __restrict__ out) {
    const int b = blockIdx.x;
    const int tid = threadIdx.x;

    __shared__ float A[NCLS][VD][VD], Cv[NCLS][VD], Mu[NCLS][VD];
    __shared__ float An[NCLS][VD][VD], Cn[NCLS][VD], Mun[NCLS][VD];
    __shared__ float norms[NCLS];
    __shared__ int selsh;

    {
        int o = tid >> 4, i = tid & 15;
        A[0][o][i] = (o == i) ? 1.f : 0.f;
    }
    if (tid < VD) {
        float s = 0.f;
        for (int ch = 0; ch < 4; ch++) s += g_part[(b * 4 + ch) * VD + tid];
        Mu[0][tid] = s * (1.0f / (float)HW) + root_b[tid];
        Cv[0][tid] = 0.f;
    }
    __syncthreads();

    for (int level = 1; level < NCLS; level++) {
        const int prevN = level, newN = level + 1;
        const int off = ((level - 1) * (level + 2)) >> 1;   // 0,2,5,9 (no local array)

        if (tid < prevN) {
            float s = 0.f;
            for (int k = 0; k < VD; k++) s += Mu[tid][k] * Mu[tid][k];
            norms[tid] = sqrtf(s);
        }
        __syncthreads();

        if (tid < newN * VD) {
            const int node = tid >> 4, o = tid & 15;
            int pl = node - 1; if (pl < 0) pl = 0;
            int pr = node;     if (pr > prevN - 1) pr = prevN - 1;
            const int ps = (pl == pr) ? pl : ((norms[pr] > norms[pl]) ? pr : pl);

            const float* W = level_w + (off + node) * (VD * VD) + o * VD;
            const float bb = level_b[(off + node) * VD + o];
            float cm = bb, mm = bb;
            float arow[VD];
#pragma unroll
            for (int i = 0; i < VD; i++) arow[i] = 0.f;
            for (int k = 0; k < VD; k++) {
                const float w = W[k];
                cm += w * Cv[ps][k];
                mm += w * Mu[ps][k];
#pragma unroll
                for (int i = 0; i < VD; i++) arow[i] += w * A[ps][k][i];
            }
            Cn[node][o] = cm;
            Mun[node][o] = mm;
#pragma unroll
            for (int i = 0; i < VD; i++) An[node][o][i] = arow[i];
        }
        __syncthreads();

        for (int idx = tid; idx < newN * VD * VD; idx += 256) {
            int node = idx >> 8, r = idx & 255;
            A[node][r >> 4][r & 15] = An[node][r >> 4][r & 15];
        }
        if (tid < newN * VD) {
            Cv[tid >> 4][tid & 15] = Cn[tid >> 4][tid & 15];
            Mu[tid >> 4][tid & 15] = Mun[tid >> 4][tid & 15];
        }
        __syncthreads();
    }

    // leaves: logits + argmax
    if (tid < NCLS) {
        float s = 0.f;
        for (int k = 0; k < VD; k++) s += Mu[tid][k] * Mu[tid][k];
        norms[tid] = sqrtf(s);
        out[b * NCLS + tid] = norms[tid];
    }
    __syncthreads();
    if (tid == 0) {
        int sel = 0; float best = norms[0];
        for (int n = 1; n < NCLS; n++) if (norms[n] > best) { best = norms[n]; sel = n; }
        selsh = sel;
        out[B * NCLS + B + b] = (float)sel;   // selected_class after logits+mantissa
    }
    __syncthreads();
    const int sel = selsh;
    g_Asel[b * 256 + tid] = A[sel][tid >> 4][tid & 15];
    if (tid < VD) {
        float s = Cv[sel][tid];
        for (int k = 0; k < VD; k++) s += A[sel][tid][k] * root_b[k];
        g_dvec[b * VD + tid] = s;
    }
}

// ======================================================================
// Pass 3: per-pixel f = A_sel@v + d, L2-normalize, MLP(64)+ReLU, scalar head,
// per-block partial sums. 8 blocks/batch, 2 pixels/thread.
// ======================================================================
__global__ void __launch_bounds__(256) k_head(const float* __restrict__ m1_w,
                                              const float* __restrict__ m1_b,
                                              const float* __restrict__ m2_w,
                                              const float* __restrict__ m2_b) {
    __shared__ float sA[VD][VD], sd[VD], sw1[64][VD], sb1[64], sw2[64];
    __shared__ float sb2;
    const int b = blockIdx.x >> 3, chunk = blockIdx.x & 7;
    const int tid = threadIdx.x;

    sA[tid >> 4][tid & 15] = g_Asel[b * 256 + tid];
    for (int i = tid; i < 64 * VD; i += 256) sw1[i >> 4][i & 15] = m1_w[i];
    if (tid < 64) { sb1[tid] = m1_b[tid]; sw2[tid] = m2_w[tid]; }
    if (tid < VD) sd[tid] = g_dvec[b * VD + tid];
    if (tid == 0) sb2 = m2_b[0];
    __syncthreads();

    float ssum = 0.f;
    const int pix0 = chunk * 512 + tid * 2;
    const float4* vp = reinterpret_cast<const float4*>(g_v + ((size_t)b * HW + pix0) * VD);

#pragma unroll
    for (int p = 0; p < 2; p++) {
        float va[VD];
#pragma unroll
        for (int q = 0; q < 4; q++) {
            float4 t = vp[p * 4 + q];
            va[4 * q + 0] = t.x; va[4 * q + 1] = t.y; va[4 * q + 2] = t.z; va[4 * q + 3] = t.w;
        }
        float f[VD];
#pragma unroll
        for (int o = 0; o < VD; o++) {
            float t = sd[o];
#pragma unroll
            for (int k = 0; k < VD; k++) t += sA[o][k] * va[k];
            f[o] = t;
        }
        float n2 = 0.f;
#pragma unroll
        for (int o = 0; o < VD; o++) n2 += f[o] * f[o];
        const float inv = 1.0f / (sqrtf(n2) + 1e-8f);

        float m2acc = 0.f;
#pragma unroll 8
        for (int j = 0; j < 64; j++) {
            float t = 0.f;
#pragma unroll
            for (int o = 0; o < VD; o++) t += sw1[j][o] * f[o];
            t = t * inv + sb1[j];
            t = fmaxf(t, 0.f);
            m2acc += sw2[j] * t;
        }
        ssum += m2acc + sb2;
    }

    // block reduce
    __shared__ float red[8];
    const int lane = tid & 31, wid = tid >> 5;
#pragma unroll
    for (int off = 16; off; off >>= 1) ssum += __shfl_xor_sync(0xffffffffu, ssum, off);
    if (lane == 0) red[wid] = ssum;
    __syncthreads();
    if (tid == 0) {
        float t = 0.f;
#pragma unroll
        for (int w = 0; w < 8; w++) t += red[w];
        g_m2part[blockIdx.x] = t;
    }
}

// ======================================================================
// Finisher: mantissa = sigmoid(mean(m2)) * 0.75 + 0.75
// ======================================================================
__global__ void k_fin(float* __restrict__ out) {
    const int b = threadIdx.x;
    if (b < B) {
        float s = 0.f;
        for (int c = 0; c < 8; c++) s += g_m2part[b * 8 + c];
        const float x = s * (1.0f / (float)HW);
        out[B * NCLS + b] = 0.75f / (1.0f + expf(-x)) + 0.75f;
    }
}

// ======================================================================
extern "C" void kernel_launch(void* const* d_in, const int* in_sizes, int n_in,
                              void* d_out, int out_size) {
    const float* features = (const float*)d_in[0];
    const float* root_w   = (const float*)d_in[1];
    const float* root_b   = (const float*)d_in[2];
    const float* level_w  = (const float*)d_in[3];
    const float* level_b  = (const float*)d_in[4];
    const float* m1_w     = (const float*)d_in[5];
    const float* m1_b     = (const float*)d_in[6];
    const float* m2_w     = (const float*)d_in[7];
    const float* m2_b     = (const float*)d_in[8];
    float* out = (float*)d_out;

    cudaFuncSetAttribute(k_root, cudaFuncAttributeMaxDynamicSharedMemorySize, 65536);

    k_root<<<B * 4, 256, 65536>>>(features, root_w);
    k_tree<<<B, 256>>>(root_b, level_w, level_b, out);
    k_head<<<B * 8, 256>>>(m1_w, m1_b, m2_w, m2_b);
    k_fin<<<1, 32>>>(out);
}

// round 8
// speedup vs baseline: 1.6968x; 1.6968x over previous
#include <cuda_runtime.h>
#include <cuda_bf16.h>
#include <cstdint>

// Problem constants
#define B     32
#define IN_CH 512
#define VD    16
#define HW    4096          // 64*64
#define NCLS  5

typedef unsigned long long ULL;

// ---------------- device scratch (no allocs allowed) ----------------
__device__ float g_v[(size_t)B * HW * VD];   // 8 MB: root conv output, (b, pix, 16)
__device__ float g_part[128 * VD];           // per-block partial sums of v (for mean)
__device__ float g_Asel[B * VD * VD];        // selected leaf composition matrix
__device__ float g_dvec[B * VD];             // selected leaf offset (A@root_b + c)
__device__ float g_m2part[256];              // per-block partial sums of m2

__device__ __forceinline__ ULL ffma2(ULL a, ULL b, ULL c) {
    ULL d;
    asm("fma.rn.f32x2 %0, %1, %2, %3;" : "=l"(d) : "l"(a), "l"(b), "l"(c));
    return d;
}
__device__ __forceinline__ ULL pack2(float lo, float hi) {
    float2 t = make_float2(lo, hi);
    return *reinterpret_cast<ULL*>(&t);
}
__device__ __forceinline__ float2 unpack2(ULL v) {
    return *reinterpret_cast<float2*>(&v);
}

// ======================================================================
// Pass 1: v[b,pix,:] = root_w @ features[b,:,pix]  (+ per-block partial sums)
// 256 threads/block, 4 consecutive pixels per thread (2 x f32x2 pairs),
// 4 blocks per batch -> grid 128 (single wave).
// Mainloop batches 8 independent LDG.128s per iteration (MLP=8) so the
// DRAM stream stays saturated; FMAs consume from registers + smem weights.
// ======================================================================
__global__ void __launch_bounds__(256) k_root(const float* __restrict__ feat,
                                              const float* __restrict__ root_w) {
    extern __shared__ ULL s_w[];   // [512][16] duplicated (w,w) pairs = 64 KB
    const int b     = blockIdx.x >> 2;
    const int chunk = blockIdx.x & 3;
    const int tid   = threadIdx.x;

    for (int idx = tid; idx < IN_CH * VD; idx += 256) {
        int c = idx >> 4, o = idx & 15;
        float w = root_w[o * IN_CH + c];
        s_w[idx] = pack2(w, w);
    }
    __syncthreads();

    const int pix0 = chunk * 1024 + tid * 4;
    const float* fp = feat + (size_t)b * (IN_CH * HW) + pix0;

    ULL acc0[VD], acc1[VD];
    {
        ULL zu = pack2(0.f, 0.f);
#pragma unroll
        for (int o = 0; o < VD; o++) { acc0[o] = zu; acc1[o] = zu; }
    }

#pragma unroll 1
    for (int c0 = 0; c0 < IN_CH; c0 += 8) {
        // front-batched: 8 independent 16B loads -> MLP_p1 = 8
        ulonglong2 x[8];
#pragma unroll
        for (int u = 0; u < 8; u++)
            x[u] = *reinterpret_cast<const ulonglong2*>(fp + (size_t)(c0 + u) * HW);

#pragma unroll
        for (int u = 0; u < 8; u++) {
            const ulonglong2* wv = reinterpret_cast<const ulonglong2*>(s_w + (c0 + u) * VD);
#pragma unroll
            for (int q = 0; q < 8; q++) {
                ulonglong2 wp = wv[q];
                acc0[2 * q + 0] = ffma2(wp.x, x[u].x, acc0[2 * q + 0]);
                acc0[2 * q + 1] = ffma2(wp.y, x[u].x, acc0[2 * q + 1]);
                acc1[2 * q + 0] = ffma2(wp.x, x[u].y, acc1[2 * q + 0]);
                acc1[2 * q + 1] = ffma2(wp.y, x[u].y, acc1[2 * q + 1]);
            }
        }
    }

    // unpack: acc0[o] = (pix0, pix0+1), acc1[o] = (pix0+2, pix0+3)
    float p0[VD], p1[VD], p2[VD], p3[VD];
#pragma unroll
    for (int o = 0; o < VD; o++) {
        float2 t0 = unpack2(acc0[o]);
        float2 t1 = unpack2(acc1[o]);
        p0[o] = t0.x; p1[o] = t0.y; p2[o] = t1.x; p3[o] = t1.y;
    }

    // store v (pixel-major, 16 contiguous floats per pixel) -> 256B/thread
    float4* vp = reinterpret_cast<float4*>(g_v + ((size_t)b * HW + pix0) * VD);
#pragma unroll
    for (int q = 0; q < 4; q++) {
        vp[0 * 4 + q] = make_float4(p0[4*q], p0[4*q+1], p0[4*q+2], p0[4*q+3]);
        vp[1 * 4 + q] = make_float4(p1[4*q], p1[4*q+1], p1[4*q+2], p1[4*q+3]);
        vp[2 * 4 + q] = make_float4(p2[4*q], p2[4*q+1], p2[4*q+2], p2[4*q+3]);
        vp[3 * 4 + q] = make_float4(p3[4*q], p3[4*q+1], p3[4*q+2], p3[4*q+3]);
    }

    // block reduction of per-pixel sums (deterministic; no atomics)
    __shared__ float red[8][VD];
    const int lane = tid & 31, wid = tid >> 5;
#pragma unroll
    for (int o = 0; o < VD; o++) {
        float s = (p0[o] + p1[o]) + (p2[o] + p3[o]);
#pragma unroll
        for (int off = 16; off; off >>= 1) s += __shfl_xor_sync(0xffffffffu, s, off);
        if (lane == 0) red[wid][o] = s;
    }
    __syncthreads();
    if (tid < VD) {
        float t = 0.f;
#pragma unroll
        for (int w = 0; w < 8; w++) t += red[w][tid];
        g_part[blockIdx.x * VD + tid] = t;
    }
}

// ======================================================================
// Pass 2: per-batch tree recursion on pooled means. One block per batch.
// ======================================================================
__global__ void __launch_bounds__(256) k_tree(const float* __restrict__ root_b,
                                              const float* __restrict__ level_w,
                                              const float* __restrict__ level_b,
                                              float* __restrict__ out) {
    const int b = blockIdx.x;
    const int tid = threadIdx.x;

    __shared__ float A[NCLS][VD][VD], Cv[NCLS][VD], Mu[NCLS][VD];
    __shared__ float An[NCLS][VD][VD], Cn[NCLS][VD], Mun[NCLS][VD];
    __shared__ float norms[NCLS];
    __shared__ int selsh;

    {
        int o = tid >> 4, i = tid & 15;
        A[0][o][i] = (o == i) ? 1.f : 0.f;
    }
    if (tid < VD) {
        float s = 0.f;
        for (int ch = 0; ch < 4; ch++) s += g_part[(b * 4 + ch) * VD + tid];
        Mu[0][tid] = s * (1.0f / (float)HW) + root_b[tid];
        Cv[0][tid] = 0.f;
    }
    __syncthreads();

    for (int level = 1; level < NCLS; level++) {
        const int prevN = level, newN = level + 1;
        const int off = ((level - 1) * (level + 2)) >> 1;   // 0,2,5,9

        if (tid < prevN) {
            float s = 0.f;
            for (int k = 0; k < VD; k++) s += Mu[tid][k] * Mu[tid][k];
            norms[tid] = sqrtf(s);
        }
        __syncthreads();

        if (tid < newN * VD) {
            const int node = tid >> 4, o = tid & 15;
            int pl = node - 1; if (pl < 0) pl = 0;
            int pr = node;     if (pr > prevN - 1) pr = prevN - 1;
            const int ps = (pl == pr) ? pl : ((norms[pr] > norms[pl]) ? pr : pl);

            const float* W = level_w + (off + node) * (VD * VD) + o * VD;
            const float bb = level_b[(off + node) * VD + o];
            float cm = bb, mm = bb;
            float arow[VD];
#pragma unroll
            for (int i = 0; i < VD; i++) arow[i] = 0.f;
            for (int k = 0; k < VD; k++) {
                const float w = W[k];
                cm += w * Cv[ps][k];
                mm += w * Mu[ps][k];
#pragma unroll
                for (int i = 0; i < VD; i++) arow[i] += w * A[ps][k][i];
            }
            Cn[node][o] = cm;
            Mun[node][o] = mm;
#pragma unroll
            for (int i = 0; i < VD; i++) An[node][o][i] = arow[i];
        }
        __syncthreads();

        for (int idx = tid; idx < newN * VD * VD; idx += 256) {
            int node = idx >> 8, r = idx & 255;
            A[node][r >> 4][r & 15] = An[node][r >> 4][r & 15];
        }
        if (tid < newN * VD) {
            Cv[tid >> 4][tid & 15] = Cn[tid >> 4][tid & 15];
            Mu[tid >> 4][tid & 15] = Mun[tid >> 4][tid & 15];
        }
        __syncthreads();
    }

    if (tid < NCLS) {
        float s = 0.f;
        for (int k = 0; k < VD; k++) s += Mu[tid][k] * Mu[tid][k];
        norms[tid] = sqrtf(s);
        out[b * NCLS + tid] = norms[tid];
    }
    __syncthreads();
    if (tid == 0) {
        int sel = 0; float best = norms[0];
        for (int n = 1; n < NCLS; n++) if (norms[n] > best) { best = norms[n]; sel = n; }
        selsh = sel;
        out[B * NCLS + B + b] = (float)sel;
    }
    __syncthreads();
    const int sel = selsh;
    g_Asel[b * 256 + tid] = A[sel][tid >> 4][tid & 15];
    if (tid < VD) {
        float s = Cv[sel][tid];
        for (int k = 0; k < VD; k++) s += A[sel][tid][k] * root_b[k];
        g_dvec[b * VD + tid] = s;
    }
}

// ======================================================================
// Pass 3: per-pixel f = A_sel@v + d, L2-normalize, MLP(64)+ReLU, scalar head.
// f32x2-packed over the thread's two pixels: lane.x = pixel0, lane.y = pixel1.
// 8 blocks/batch, 2 pixels/thread.
// ======================================================================
__global__ void __launch_bounds__(256) k_head(const float* __restrict__ m1_w,
                                              const float* __restrict__ m1_b,
                                              const float* __restrict__ m2_w,
                                              const float* __restrict__ m2_b) {
    __shared__ ULL sAp[VD * VD];      // A_sel duplicated pairs (2 KB)
    __shared__ ULL sdp[VD];           // d duplicated pairs
    __shared__ ULL sw1p[64 * VD];     // m1_w duplicated pairs (8 KB)
    __shared__ ULL sb1p[64];          // m1_b duplicated pairs
    __shared__ float sw2[64];
    __shared__ float sb2;
    const int b = blockIdx.x >> 3, chunk = blockIdx.x & 7;
    const int tid = threadIdx.x;

    {
        float a = g_Asel[b * 256 + tid];
        sAp[tid] = pack2(a, a);
    }
    for (int i = tid; i < 64 * VD; i += 256) {
        float w = m1_w[i];
        sw1p[i] = pack2(w, w);
    }
    if (tid < 64) {
        float bb = m1_b[tid];
        sb1p[tid] = pack2(bb, bb);
        sw2[tid] = m2_w[tid];
    }
    if (tid < VD) {
        float dv = g_dvec[b * VD + tid];
        sdp[tid] = pack2(dv, dv);
    }
    if (tid == 0) sb2 = m2_b[0];
    __syncthreads();

    const int pix0 = chunk * 512 + tid * 2;
    const float4* vp = reinterpret_cast<const float4*>(g_v + ((size_t)b * HW + pix0) * VD);

    // load both pixels, pack channel-wise: v2[k] = (v_p0[k], v_p1[k])
    float va0[VD], va1[VD];
#pragma unroll
    for (int q = 0; q < 4; q++) {
        float4 t0 = vp[q], t1 = vp[4 + q];
        va0[4*q+0] = t0.x; va0[4*q+1] = t0.y; va0[4*q+2] = t0.z; va0[4*q+3] = t0.w;
        va1[4*q+0] = t1.x; va1[4*q+1] = t1.y; va1[4*q+2] = t1.z; va1[4*q+3] = t1.w;
    }
    ULL v2[VD];
#pragma unroll
    for (int k = 0; k < VD; k++) v2[k] = pack2(va0[k], va1[k]);

    // f = A@v + d  (packed)
    ULL f2[VD];
#pragma unroll
    for (int o = 0; o < VD; o++) {
        ULL t = sdp[o];
#pragma unroll
        for (int k = 0; k < VD; k++) t = ffma2(sAp[o * VD + k], v2[k], t);
        f2[o] = t;
    }

    // per-pixel 1/(||f||+eps), packed back
    float n20 = 0.f, n21 = 0.f;
#pragma unroll
    for (int o = 0; o < VD; o++) {
        float2 t = unpack2(f2[o]);
        n20 += t.x * t.x; n21 += t.y * t.y;
    }
    const ULL inv2 = pack2(1.0f / (sqrtf(n20) + 1e-8f),
                           1.0f / (sqrtf(n21) + 1e-8f));

    // MLP: t = relu((w1.f)*inv + b1); m2 += w2*t   (dot packed, relu scalar)
    float m2a0 = 0.f, m2a1 = 0.f;
#pragma unroll 8
    for (int j = 0; j < 64; j++) {
        ULL t2 = pack2(0.f, 0.f);
#pragma unroll
        for (int o = 0; o < VD; o++) t2 = ffma2(sw1p[j * VD + o], f2[o], t2);
        t2 = ffma2(t2, inv2, sb1p[j]);
        float2 t = unpack2(t2);
        m2a0 += sw2[j] * fmaxf(t.x, 0.f);
        m2a1 += sw2[j] * fmaxf(t.y, 0.f);
    }
    float ssum = (m2a0 + m2a1) + 2.0f * sb2;

    // block reduce
    __shared__ float red[8];
    const int lane = tid & 31, wid = tid >> 5;
#pragma unroll
    for (int off = 16; off; off >>= 1) ssum += __shfl_xor_sync(0xffffffffu, ssum, off);
    if (lane == 0) red[wid] = ssum;
    __syncthreads();
    if (tid == 0) {
        float t = 0.f;
#pragma unroll
        for (int w = 0; w < 8; w++) t += red[w];
        g_m2part[blockIdx.x] = t;
    }
}

// ======================================================================
// Finisher: mantissa = sigmoid(mean(m2)) * 0.75 + 0.75
// ======================================================================
__global__ void k_fin(float* __restrict__ out) {
    const int b = threadIdx.x;
    if (b < B) {
        float s = 0.f;
        for (int c = 0; c < 8; c++) s += g_m2part[b * 8 + c];
        const float x = s * (1.0f / (float)HW);
        out[B * NCLS + b] = 0.75f / (1.0f + expf(-x)) + 0.75f;
    }
}

// ======================================================================
extern "C" void kernel_launch(void* const* d_in, const int* in_sizes, int n_in,
                              void* d_out, int out_size) {
    const float* features = (const float*)d_in[0];
    const float* root_w   = (const float*)d_in[1];
    const float* root_b   = (const float*)d_in[2];
    const float* level_w  = (const float*)d_in[3];
    const float* level_b  = (const float*)d_in[4];
    const float* m1_w     = (const float*)d_in[5];
    const float* m1_b     = (const float*)d_in[6];
    const float* m2_w     = (const float*)d_in[7];
    const float* m2_b     = (const float*)d_in[8];
    float* out = (float*)d_out;

    cudaFuncSetAttribute(k_root, cudaFuncAttributeMaxDynamicSharedMemorySize, 65536);

    k_root<<<B * 4, 256, 65536>>>(features, root_w);
    k_tree<<<B, 256>>>(root_b, level_w, level_b, out);
    k_head<<<B * 8, 256>>>(m1_w, m1_b, m2_w, m2_b);
    k_fin<<<1, 32>>>(out);
}

// round 9
// speedup vs baseline: 1.7255x; 1.0169x over previous
#include <cuda_runtime.h>
#include <cuda_bf16.h>
#include <cstdint>

// Problem constants
#define B     32
#define IN_CH 512
#define VD    16
#define HW    4096          // 64*64
#define NCLS  5

typedef unsigned long long ULL;

// ---------------- device scratch (no allocs allowed) ----------------
__device__ float g_v[(size_t)B * HW * VD];   // 8 MB: root conv output, (b, pix, 16)
__device__ float g_part[128 * VD];           // per-block partial sums of v (for mean)
__device__ float g_Asel[B * VD * VD];        // selected leaf composition matrix
__device__ float g_dvec[B * VD];             // selected leaf offset (A@root_b + c)
__device__ float g_m2part[256];              // per-block partial sums of m2

__device__ __forceinline__ ULL ffma2(ULL a, ULL b, ULL c) {
    ULL d;
    asm("fma.rn.f32x2 %0, %1, %2, %3;" : "=l"(d) : "l"(a), "l"(b), "l"(c));
    return d;
}
__device__ __forceinline__ ULL pack2(float lo, float hi) {
    float2 t = make_float2(lo, hi);
    return *reinterpret_cast<ULL*>(&t);
}
__device__ __forceinline__ float2 unpack2(ULL v) {
    return *reinterpret_cast<float2*>(&v);
}

// ======================================================================
// Pass 1: v[b,pix,:] = root_w @ features[b,:,pix]  (+ per-block partial sums)
// 256 threads/block, 4 consecutive pixels per thread (2 x f32x2 pairs),
// 4 blocks per batch -> grid 128 (single wave).
// Mainloop batches 8 independent LDG.128s per iteration (MLP=8) so the
// DRAM stream stays saturated; FMAs consume from registers + smem weights.
// ======================================================================
__global__ void __launch_bounds__(256) k_root(const float* __restrict__ feat,
                                              const float* __restrict__ root_w) {
    extern __shared__ ULL s_w[];   // [512][16] duplicated (w,w) pairs = 64 KB
    const int b     = blockIdx.x >> 2;
    const int chunk = blockIdx.x & 3;
    const int tid   = threadIdx.x;

    for (int idx = tid; idx < IN_CH * VD; idx += 256) {
        int c = idx >> 4, o = idx & 15;
        float w = root_w[o * IN_CH + c];
        s_w[idx] = pack2(w, w);
    }
    __syncthreads();

    const int pix0 = chunk * 1024 + tid * 4;
    const float* fp = feat + (size_t)b * (IN_CH * HW) + pix0;

    ULL acc0[VD], acc1[VD];
    {
        ULL zu = pack2(0.f, 0.f);
#pragma unroll
        for (int o = 0; o < VD; o++) { acc0[o] = zu; acc1[o] = zu; }
    }

#pragma unroll 1
    for (int c0 = 0; c0 < IN_CH; c0 += 8) {
        // front-batched: 8 independent 16B loads -> MLP_p1 = 8
        ulonglong2 x[8];
#pragma unroll
        for (int u = 0; u < 8; u++)
            x[u] = *reinterpret_cast<const ulonglong2*>(fp + (size_t)(c0 + u) * HW);

#pragma unroll
        for (int u = 0; u < 8; u++) {
            const ulonglong2* wv = reinterpret_cast<const ulonglong2*>(s_w + (c0 + u) * VD);
#pragma unroll
            for (int q = 0; q < 8; q++) {
                ulonglong2 wp = wv[q];
                acc0[2 * q + 0] = ffma2(wp.x, x[u].x, acc0[2 * q + 0]);
                acc0[2 * q + 1] = ffma2(wp.y, x[u].x, acc0[2 * q + 1]);
                acc1[2 * q + 0] = ffma2(wp.x, x[u].y, acc1[2 * q + 0]);
                acc1[2 * q + 1] = ffma2(wp.y, x[u].y, acc1[2 * q + 1]);
            }
        }
    }

    // unpack: acc0[o] = (pix0, pix0+1), acc1[o] = (pix0+2, pix0+3)
    float p0[VD], p1[VD], p2[VD], p3[VD];
#pragma unroll
    for (int o = 0; o < VD; o++) {
        float2 t0 = unpack2(acc0[o]);
        float2 t1 = unpack2(acc1[o]);
        p0[o] = t0.x; p1[o] = t0.y; p2[o] = t1.x; p3[o] = t1.y;
    }

    // store v (pixel-major, 16 contiguous floats per pixel) -> 256B/thread
    float4* vp = reinterpret_cast<float4*>(g_v + ((size_t)b * HW + pix0) * VD);
#pragma unroll
    for (int q = 0; q < 4; q++) {
        vp[0 * 4 + q] = make_float4(p0[4*q], p0[4*q+1], p0[4*q+2], p0[4*q+3]);
        vp[1 * 4 + q] = make_float4(p1[4*q], p1[4*q+1], p1[4*q+2], p1[4*q+3]);
        vp[2 * 4 + q] = make_float4(p2[4*q], p2[4*q+1], p2[4*q+2], p2[4*q+3]);
        vp[3 * 4 + q] = make_float4(p3[4*q], p3[4*q+1], p3[4*q+2], p3[4*q+3]);
    }

    // block reduction of per-pixel sums (deterministic; no atomics)
    __shared__ float red[8][VD];
    const int lane = tid & 31, wid = tid >> 5;
#pragma unroll
    for (int o = 0; o < VD; o++) {
        float s = (p0[o] + p1[o]) + (p2[o] + p3[o]);
#pragma unroll
        for (int off = 16; off; off >>= 1) s += __shfl_xor_sync(0xffffffffu, s, off);
        if (lane == 0) red[wid][o] = s;
    }
    __syncthreads();
    if (tid < VD) {
        float t = 0.f;
#pragma unroll
        for (int w = 0; w < 8; w++) t += red[w][tid];
        g_part[blockIdx.x * VD + tid] = t;
    }
}

// ======================================================================
// Pass 2: per-batch tree recursion on pooled means. One block per batch.
// ======================================================================
__global__ void __launch_bounds__(256) k_tree(const float* __restrict__ root_b,
                                              const float* __restrict__ level_w,
                                              const float* __restrict__ level_b,
                                              float* __restrict__ out) {
    const int b = blockIdx.x;
    const int tid = threadIdx.x;

    __shared__ float A[NCLS][VD][VD], Cv[NCLS][VD], Mu[NCLS][VD];
    __shared__ float An[NCLS][VD][VD], Cn[NCLS][VD], Mun[NCLS][VD];
    __shared__ float norms[NCLS];
    __shared__ int selsh;

    {
        int o = tid >> 4, i = tid & 15;
        A[0][o][i] = (o == i) ? 1.f : 0.f;
    }
    if (tid < VD) {
        float s = 0.f;
        for (int ch = 0; ch < 4; ch++) s += g_part[(b * 4 + ch) * VD + tid];
        Mu[0][tid] = s * (1.0f / (float)HW) + root_b[tid];
        Cv[0][tid] = 0.f;
    }
    __syncthreads();

    for (int level = 1; level < NCLS; level++) {
        const int prevN = level, newN = level + 1;
        const int off = ((level - 1) * (level + 2)) >> 1;   // 0,2,5,9

        if (tid < prevN) {
            float s = 0.f;
            for (int k = 0; k < VD; k++) s += Mu[tid][k] * Mu[tid][k];
            norms[tid] = sqrtf(s);
        }
        __syncthreads();

        if (tid < newN * VD) {
            const int node = tid >> 4, o = tid & 15;
            int pl = node - 1; if (pl < 0) pl = 0;
            int pr = node;     if (pr > prevN - 1) pr = prevN - 1;
            const int ps = (pl == pr) ? pl : ((norms[pr] > norms[pl]) ? pr : pl);

            const float* W = level_w + (off + node) * (VD * VD) + o * VD;
            const float bb = level_b[(off + node) * VD + o];
            float cm = bb, mm = bb;
            float arow[VD];
#pragma unroll
            for (int i = 0; i < VD; i++) arow[i] = 0.f;
            for (int k = 0; k < VD; k++) {
                const float w = W[k];
                cm += w * Cv[ps][k];
                mm += w * Mu[ps][k];
#pragma unroll
                for (int i = 0; i < VD; i++) arow[i] += w * A[ps][k][i];
            }
            Cn[node][o] = cm;
            Mun[node][o] = mm;
#pragma unroll
            for (int i = 0; i < VD; i++) An[node][o][i] = arow[i];
        }
        __syncthreads();

        for (int idx = tid; idx < newN * VD * VD; idx += 256) {
            int node = idx >> 8, r = idx & 255;
            A[node][r >> 4][r & 15] = An[node][r >> 4][r & 15];
        }
        if (tid < newN * VD) {
            Cv[tid >> 4][tid & 15] = Cn[tid >> 4][tid & 15];
            Mu[tid >> 4][tid & 15] = Mun[tid >> 4][tid & 15];
        }
        __syncthreads();
    }

    if (tid < NCLS) {
        float s = 0.f;
        for (int k = 0; k < VD; k++) s += Mu[tid][k] * Mu[tid][k];
        norms[tid] = sqrtf(s);
        out[b * NCLS + tid] = norms[tid];
    }
    __syncthreads();
    if (tid == 0) {
        int sel = 0; float best = norms[0];
        for (int n = 1; n < NCLS; n++) if (norms[n] > best) { best = norms[n]; sel = n; }
        selsh = sel;
        out[B * NCLS + B + b] = (float)sel;
    }
    __syncthreads();
    const int sel = selsh;
    g_Asel[b * 256 + tid] = A[sel][tid >> 4][tid & 15];
    if (tid < VD) {
        float s = Cv[sel][tid];
        for (int k = 0; k < VD; k++) s += A[sel][tid][k] * root_b[k];
        g_dvec[b * VD + tid] = s;
    }
}

// ======================================================================
// Pass 3: per-pixel f = A_sel@v + d, L2-normalize, MLP(64)+ReLU, scalar head.
// f32x2-packed over the thread's two pixels: lane.x = pixel0, lane.y = pixel1.
// 8 blocks/batch, 2 pixels/thread.
// ======================================================================
__global__ void __launch_bounds__(256) k_head(const float* __restrict__ m1_w,
                                              const float* __restrict__ m1_b,
                                              const float* __restrict__ m2_w,
                                              const float* __restrict__ m2_b) {
    __shared__ ULL sAp[VD * VD];      // A_sel duplicated pairs (2 KB)
    __shared__ ULL sdp[VD];           // d duplicated pairs
    __shared__ ULL sw1p[64 * VD];     // m1_w duplicated pairs (8 KB)
    __shared__ ULL sb1p[64];          // m1_b duplicated pairs
    __shared__ float sw2[64];
    __shared__ float sb2;
    const int b = blockIdx.x >> 3, chunk = blockIdx.x & 7;
    const int tid = threadIdx.x;

    {
        float a = g_Asel[b * 256 + tid];
        sAp[tid] = pack2(a, a);
    }
    for (int i = tid; i < 64 * VD; i += 256) {
        float w = m1_w[i];
        sw1p[i] = pack2(w, w);
    }
    if (tid < 64) {
        float bb = m1_b[tid];
        sb1p[tid] = pack2(bb, bb);
        sw2[tid] = m2_w[tid];
    }
    if (tid < VD) {
        float dv = g_dvec[b * VD + tid];
        sdp[tid] = pack2(dv, dv);
    }
    if (tid == 0) sb2 = m2_b[0];
    __syncthreads();

    const int pix0 = chunk * 512 + tid * 2;
    const float4* vp = reinterpret_cast<const float4*>(g_v + ((size_t)b * HW + pix0) * VD);

    // load both pixels, pack channel-wise: v2[k] = (v_p0[k], v_p1[k])
    float va0[VD], va1[VD];
#pragma unroll
    for (int q = 0; q < 4; q++) {
        float4 t0 = vp[q], t1 = vp[4 + q];
        va0[4*q+0] = t0.x; va0[4*q+1] = t0.y; va0[4*q+2] = t0.z; va0[4*q+3] = t0.w;
        va1[4*q+0] = t1.x; va1[4*q+1] = t1.y; va1[4*q+2] = t1.z; va1[4*q+3] = t1.w;
    }
    ULL v2[VD];
#pragma unroll
    for (int k = 0; k < VD; k++) v2[k] = pack2(va0[k], va1[k]);

    // f = A@v + d  (packed)
    ULL f2[VD];
#pragma unroll
    for (int o = 0; o < VD; o++) {
        ULL t = sdp[o];
#pragma unroll
        for (int k = 0; k < VD; k++) t = ffma2(sAp[o * VD + k], v2[k], t);
        f2[o] = t;
    }

    // per-pixel 1/(||f||+eps), packed back
    float n20 = 0.f, n21 = 0.f;
#pragma unroll
    for (int o = 0; o < VD; o++) {
        float2 t = unpack2(f2[o]);
        n20 += t.x * t.x; n21 += t.y * t.y;
    }
    const ULL inv2 = pack2(1.0f / (sqrtf(n20) + 1e-8f),
                           1.0f / (sqrtf(n21) + 1e-8f));

    // MLP: t = relu((w1.f)*inv + b1); m2 += w2*t   (dot packed, relu scalar)
    float m2a0 = 0.f, m2a1 = 0.f;
#pragma unroll 8
    for (int j = 0; j < 64; j++) {
        ULL t2 = pack2(0.f, 0.f);
#pragma unroll
        for (int o = 0; o < VD; o++) t2 = ffma2(sw1p[j * VD + o], f2[o], t2);
        t2 = ffma2(t2, inv2, sb1p[j]);
        float2 t = unpack2(t2);
        m2a0 += sw2[j] * fmaxf(t.x, 0.f);
        m2a1 += sw2[j] * fmaxf(t.y, 0.f);
    }
    float ssum = (m2a0 + m2a1) + 2.0f * sb2;

    // block reduce
    __shared__ float red[8];
    const int lane = tid & 31, wid = tid >> 5;
#pragma unroll
    for (int off = 16; off; off >>= 1) ssum += __shfl_xor_sync(0xffffffffu, ssum, off);
    if (lane == 0) red[wid] = ssum;
    __syncthreads();
    if (tid == 0) {
        float t = 0.f;
#pragma unroll
        for (int w = 0; w < 8; w++) t += red[w];
        g_m2part[blockIdx.x] = t;
    }
}

// ======================================================================
// Finisher: mantissa = sigmoid(mean(m2)) * 0.75 + 0.75
// ======================================================================
__global__ void k_fin(float* __restrict__ out) {
    const int b = threadIdx.x;
    if (b < B) {
        float s = 0.f;
        for (int c = 0; c < 8; c++) s += g_m2part[b * 8 + c];
        const float x = s * (1.0f / (float)HW);
        out[B * NCLS + b] = 0.75f / (1.0f + expf(-x)) + 0.75f;
    }
}

// ======================================================================
extern "C" void kernel_launch(void* const* d_in, const int* in_sizes, int n_in,
                              void* d_out, int out_size) {
    const float* features = (const float*)d_in[0];
    const float* root_w   = (const float*)d_in[1];
    const float* root_b   = (const float*)d_in[2];
    const float* level_w  = (const float*)d_in[3];
    const float* level_b  = (const float*)d_in[4];
    const float* m1_w     = (const float*)d_in[5];
    const float* m1_b     = (const float*)d_in[6];
    const float* m2_w     = (const float*)d_in[7];
    const float* m2_b     = (const float*)d_in[8];
    float* out = (float*)d_out;

    cudaFuncSetAttribute(k_root, cudaFuncAttributeMaxDynamicSharedMemorySize, 65536);

    k_root<<<B * 4, 256, 65536>>>(features, root_w);
    k_tree<<<B, 256>>>(root_b, level_w, level_b, out);
    k_head<<<B * 8, 256>>>(m1_w, m1_b, m2_w, m2_b);
    k_fin<<<1, 32>>>(out);
}